// round 3
// baseline (speedup 1.0000x reference)
#include <cuda_runtime.h>
#include <cstdint>

// BidPrefix: per row of 302 floats = [rates[0..299], market_price, bid]
//   cp1[j] = prod_{k<j} rates[k]  (cp1[0]=1)
//   survival  = cp1[bid]                 (bid in [0,300])
//   rate_last = cp1[mp] - cp1[mp+1]      (mp  in [0,299])
// One warp per row, float2 coalesced loads, warp shuffle product-scan,
// early exit past max(bid-1, mp).
//
// Capture rule: chunk [base, base+63] captures cp1[base .. base+63].
// After the loop, run == cp1[processed]. The single uncapturable case is
// bid == processed (bid multiple of 64 ending the loop, incl. bid==300 when
// clamped) -> detect via p_bid == 0 (all true prefix products are > 0).

static constexpr int SEQ = 300;
static constexpr int ROW = 302;

__global__ __launch_bounds__(256) void bidprefix_kernel(
    const float* __restrict__ in, float* __restrict__ out, int batch)
{
    const int warp_id = (blockIdx.x * blockDim.x + threadIdx.x) >> 5;
    const int lane    = threadIdx.x & 31;
    if (warp_id >= batch) return;

    const float* row = in + (size_t)warp_id * ROW;

    // tail: [300]=market_price, [301]=bid ; 8B aligned (302 even, 300 even)
    const float2 tail = *reinterpret_cast<const float2*>(row + SEQ);
    const int mp  = (int)tail.x;   // 0..299
    const int bid = (int)tail.y;   // 0..300

    const int maxelem = max(bid - 1, mp);   // highest rate index needed (>=0)

    float run   = 1.0f;   // product of all rates before current chunk
    float p_bid = 0.0f;   // cp1[bid]   (captured by the matching lane)
    float p_mp  = 0.0f;   // cp1[mp]
    float r_mp  = 0.0f;   // rates[mp]

    for (int base = 0; base <= maxelem; base += 64) {
        const int i0 = base + 2 * lane;     // even, 8B aligned
        float2 v = make_float2(1.0f, 1.0f);
        if (i0 < SEQ)
            v = *reinterpret_cast<const float2*>(row + i0);

        const float q2 = v.x * v.y;         // product of this lane's pair

        // inclusive warp scan (product)
        float s = q2;
        #pragma unroll
        for (int off = 1; off < 32; off <<= 1) {
            const float t = __shfl_up_sync(0xffffffffu, s, off);
            if (lane >= off) s *= t;
        }
        // exclusive prefix for this lane
        float excl = __shfl_up_sync(0xffffffffu, s, 1);
        if (lane == 0) excl = 1.0f;

        const float P0 = run * excl;        // cp1[i0]
        const float P1 = P0 * v.x;          // cp1[i0+1]

        if (i0     == bid) p_bid = P0;
        if (i0 + 1 == bid) p_bid = P1;
        if (i0     == mp)  { p_mp = P0; r_mp = v.x; }
        if (i0 + 1 == mp)  { p_mp = P1; r_mp = v.y; }

        run *= __shfl_sync(0xffffffffu, s, 31);   // full chunk product
    }

    // gather the unique nonzero per-warp values (all products are > 0)
    #pragma unroll
    for (int off = 16; off; off >>= 1) {
        p_bid = fmaxf(p_bid, __shfl_xor_sync(0xffffffffu, p_bid, off));
        p_mp  = fmaxf(p_mp,  __shfl_xor_sync(0xffffffffu, p_mp,  off));
        r_mp  = fmaxf(r_mp,  __shfl_xor_sync(0xffffffffu, r_mp,  off));
    }

    if (lane == 0) {
        // p_bid==0 <=> bid was exactly the number of processed elements,
        // in which case run == cp1[bid].
        const float survival  = (p_bid > 0.0f) ? p_bid : run;
        const float rate_last = p_mp - p_mp * r_mp;  // cp1[mp] - cp1[mp+1]
        out[warp_id]         = survival;
        out[batch + warp_id] = rate_last;
    }
}

extern "C" void kernel_launch(void* const* d_in, const int* in_sizes, int n_in,
                              void* d_out, int out_size)
{
    const float* in  = (const float*)d_in[0];
    float*       out = (float*)d_out;
    const int batch  = in_sizes[0] / ROW;   // 500000

    const int threads = 256;                 // 8 warps -> 8 rows per block
    const int warps_per_block = threads / 32;
    const int blocks = (batch + warps_per_block - 1) / warps_per_block;
    bidprefix_kernel<<<blocks, threads>>>(in, out, batch);
}

// round 4
// speedup vs baseline: 1.6272x; 1.6272x over previous
#include <cuda_runtime.h>
#include <cstdint>

// BidPrefix: row = [rates[0..299], market_price, bid]
//   cp1[j] = prod_{k<j} rates[k]
//   out[0:B]  = cp1[bid]            (bid in [0,300])
//   out[B:2B] = cp1[mp] - cp1[mp+1] (mp  in [0,299])
//
// One warp per row. Lane t (t<30) owns rates[10t .. 10t+9] (contiguous, so the
// warp still consumes whole 32B sectors). Per lane: serial product chain whose
// intermediates are the inner exclusive prefixes q_0..q_9 (q_0=1). ONE warp
// shuffle-scan over lane products gives cross-lane exclusive prefix excl_t.
// Then cp1[x] = shfl.idx(excl, x/10) * q[x/10][x%10], answered generically for
// x in {bid, mp, mp+1} via padded smem (stride 11 -> bank-conflict-free).
// Lane 30's excl = cp1[300], q_0 = 1, so x=300 needs no special case.
// Lanes with 10t > max(bid-1, mp) skip their loads (DRAM early-exit).

static constexpr int SEQ = 300;
static constexpr int ROW = 302;
static constexpr int EPL = 10;       // elements per lane (lanes 0..29)
static constexpr int QSTRIDE = 11;   // gcd(11,32)=1 -> conflict-free STS
static constexpr int WARPS = 8;

__global__ __launch_bounds__(256) void bidprefix_kernel(
    const float* __restrict__ in, float* __restrict__ out, int batch)
{
    __shared__ float qsm[WARPS][31 * QSTRIDE];   // lanes 0..30 region, ~10.9KB

    const int wib  = threadIdx.x >> 5;
    const int lane = threadIdx.x & 31;
    const int warp_id = blockIdx.x * WARPS + wib;
    if (warp_id >= batch) return;

    const float* row = in + (size_t)warp_id * ROW;

    // tail: [300]=mp, [301]=bid ; base 8B-aligned (302 & 300 even)
    const float2 tail = *reinterpret_cast<const float2*>(row + SEQ);
    const int mp  = (int)tail.x;            // 0..299
    const int bid = (int)tail.y;            // 0..300
    const int maxelem = max(bid - 1, mp);   // highest rate index needed

    const int g0 = lane * EPL;              // even -> 8B-aligned float2 loads
    float2 a = make_float2(1.f, 1.f), b = a, c = a, d = a, e = a;
    if (g0 <= maxelem) {                    // lanes 30,31 (g0>=300) never load
        a = *reinterpret_cast<const float2*>(row + g0);
        b = *reinterpret_cast<const float2*>(row + g0 + 2);
        c = *reinterpret_cast<const float2*>(row + g0 + 4);
        d = *reinterpret_cast<const float2*>(row + g0 + 6);
        e = *reinterpret_cast<const float2*>(row + g0 + 8);
    }

    // serial chain: q[j] = prod of first j local elems (exclusive prefixes)
    float q1 = a.x;
    float q2 = q1 * a.y;
    float q3 = q2 * b.x;
    float q4 = q3 * b.y;
    float q5 = q4 * c.x;
    float q6 = q5 * c.y;
    float q7 = q6 * d.x;
    float q8 = q7 * d.y;
    float q9 = q8 * e.x;
    const float s = q9 * e.y;               // full local product

    // stash inner prefixes for the generic queries
    float* qs = &qsm[wib][(lane < 31 ? lane : 31 - 1) * 0 + lane * 0];  // (placate compiler)
    if (lane <= 30) {
        float* p = &qsm[wib][lane * QSTRIDE];
        p[0] = 1.0f; p[1] = q1; p[2] = q2; p[3] = q3; p[4] = q4;
        p[5] = q5;   p[6] = q6; p[7] = q7; p[8] = q8; p[9] = q9;
    }
    (void)qs;

    // one inclusive warp scan (product) over lane products
    float incl = s;
    #pragma unroll
    for (int off = 1; off < 32; off <<= 1) {
        const float t = __shfl_up_sync(0xffffffffu, incl, off);
        if (lane >= off) incl *= t;
    }
    float excl = __shfl_up_sync(0xffffffffu, incl, 1);
    if (lane == 0) excl = 1.0f;

    __syncwarp();                            // STS -> LDS visibility

    // generic query: cp1[x] = excl_{x/10} * q_{x/10}[x%10]   (x in [0,300])
    const float* qbase = &qsm[wib][0];
    auto Q = [&](int x) -> float {
        const int dd = x / EPL;
        const int mm = x - dd * EPL;
        const float ee = __shfl_sync(0xffffffffu, excl, dd);
        return ee * qbase[dd * QSTRIDE + mm];
    };

    const float surv = Q(bid);
    const float c0   = Q(mp);
    const float c1   = Q(mp + 1);

    if (lane == 0) {
        out[warp_id]         = surv;
        out[batch + warp_id] = c0 - c1;
    }
}

extern "C" void kernel_launch(void* const* d_in, const int* in_sizes, int n_in,
                              void* d_out, int out_size)
{
    const float* in  = (const float*)d_in[0];
    float*       out = (float*)d_out;
    const int batch  = in_sizes[0] / ROW;    // 500000

    const int threads = 32 * WARPS;          // 256
    const int blocks  = (batch + WARPS - 1) / WARPS;
    bidprefix_kernel<<<blocks, threads>>>(in, out, batch);
}